// round 15
// baseline (speedup 1.0000x reference)
#include <cuda_runtime.h>
#include <math.h>

#define Bb 64
#define Nn 1024
#define Hh 64
#define Tt 10

// ---------------- scratch (device globals; permuted row space) -----------------
__device__ __align__(16) float g_nrmP[Bb*Nn*Hh];   // emb/||emb||, bucket order
__device__ __align__(16) float g_xw0 [Bb*Nn*Hh];   // emb @ W0^T
__device__ __align__(16) float g_xw1 [Bb*Nn*Hh];   // h1  @ W1^T
__device__ __align__(16) float g_h2P [Bb*Nn*Hh];
__device__ __align__(16) float g_G   [Bb*Tt*Hh*Hh];
__device__ __align__(16) float g_M   [Bb*Tt*Hh*Hh];
__device__ int g_pos[Bb*Nn];
__device__ int g_off[Bb*Tt];
__device__ int g_cnt[Bb*Tt];
__device__ __align__(16) float g_ctx[Bb*Hh];
__device__ int g_bsync[Bb] = {0};                  // per-batch gmat arrival counter

#define FMA4(A, s, v) { (A).x += (s)*(v).x; (A).y += (s)*(v).y; (A).z += (s)*(v).z; (A).w += (s)*(v).w; }
#define GDC_WAIT()   asm volatile("griddepcontrol.wait;" ::: "memory")
#define GDC_LAUNCH() asm volatile("griddepcontrol.launch_dependents;" ::: "memory")

// ---------------- K0: bucket ----------------------------------------------------
__global__ __launch_bounds__(1024) void k_bucket(const int* __restrict__ types)
{
    __shared__ int s_cnt[16];
    __shared__ int s_off[16];
    int b = blockIdx.x, n = threadIdx.x;
    if (n < Tt) s_cnt[n] = 0;
    if (n < 64) g_ctx[b*64 + n] = 0.f;
    __syncthreads();
    int t = types[b*Nn + n];
    int rank = atomicAdd(&s_cnt[t], 1);
    __syncthreads();
    if (n == 0) {
        int a = 0;
        #pragma unroll
        for (int i = 0; i < Tt; ++i) { s_off[i] = a; a += s_cnt[i]; }
    }
    __syncthreads();
    g_pos[b*Nn + n] = b*Nn + s_off[t] + rank;
    if (n < Tt) { g_cnt[b*Tt + n] = s_cnt[n]; g_off[b*Tt + n] = s_off[n]; }
    GDC_LAUNCH();
}

// ---------------- K1: encoder -> nrmP + HW0 = emb @ W0^T ------------------------
__global__ __launch_bounds__(256) void k_enc(
    const float* __restrict__ tf,
    const float* __restrict__ w1, const float* __restrict__ b1,
    const float* __restrict__ w2, const float* __restrict__ b2,
    const float* __restrict__ gw)
{
    __shared__ __align__(16) float s_A[64*68];
    __shared__ __align__(16) float s_B[64*68];
    __shared__ __align__(16) float s_f[192];
    __shared__ __align__(16) float s_w1[192];
    __shared__ __align__(16) float s_b1[64];
    __shared__ __align__(16) float s_b2[64];
    int tid = threadIdx.x;
    int tx = tid & 15, ty = tid >> 4;
    int base = blockIdx.x * 64;

    #pragma unroll
    for (int it = 0; it < 16; ++it) {
        int e = tid + it*256;
        int j = e >> 6, k = e & 63;
        s_B[k*68 + j] = w2[e];                 // w2^T
    }
    if (tid < 192) { s_f[tid] = tf[base*3 + tid]; s_w1[tid] = w1[tid]; }
    if (tid < 64)  { s_b1[tid] = b1[tid]; s_b2[tid] = b2[tid]; }
    __syncthreads();
    GDC_LAUNCH();

    #pragma unroll
    for (int it = 0; it < 16; ++it) {
        int e = tid + it*256;
        int row = e >> 6, k = e & 63;
        float h = s_f[row*3+0]*s_w1[k*3+0] + s_f[row*3+1]*s_w1[k*3+1]
                + s_f[row*3+2]*s_w1[k*3+2] + s_b1[k];
        s_A[row*68 + k] = fmaxf(h, 0.f);
    }
    __syncthreads();

    // emb = h1 @ w2^T + b2
    float4 acc[4];
    #pragma unroll
    for (int i = 0; i < 4; ++i) acc[i] = make_float4(0.f,0.f,0.f,0.f);
    #pragma unroll 8
    for (int kk = 0; kk < 64; ++kk) {
        float4 bb = *(const float4*)&s_B[kk*68 + tx*4];
        float a0 = s_A[(ty*4+0)*68 + kk];
        float a1 = s_A[(ty*4+1)*68 + kk];
        float a2 = s_A[(ty*4+2)*68 + kk];
        float a3 = s_A[(ty*4+3)*68 + kk];
        FMA4(acc[0], a0, bb); FMA4(acc[1], a1, bb);
        FMA4(acc[2], a2, bb); FMA4(acc[3], a3, bb);
    }
    float4 bias = *(const float4*)&s_b2[tx*4];
    GDC_WAIT();
    int p[4];
    #pragma unroll
    for (int i = 0; i < 4; ++i) {
        acc[i].x += bias.x; acc[i].y += bias.y;
        acc[i].z += bias.z; acc[i].w += bias.w;
        float sq = acc[i].x*acc[i].x + acc[i].y*acc[i].y
                 + acc[i].z*acc[i].z + acc[i].w*acc[i].w;
        #pragma unroll
        for (int o = 8; o > 0; o >>= 1) sq += __shfl_xor_sync(0xffffffffu, sq, o);
        float inv = 1.f / fmaxf(sqrtf(sq), 1e-12f);
        p[i] = g_pos[base + ty*4 + i];
        float4 nv = make_float4(acc[i].x*inv, acc[i].y*inv, acc[i].z*inv, acc[i].w*inv);
        *(float4*)&g_nrmP[p[i]*64 + tx*4] = nv;
    }
    __syncthreads();

    // restage: s_A = emb tile, s_B = W0^T
    #pragma unroll
    for (int i = 0; i < 4; ++i)
        *(float4*)&s_A[(ty*4+i)*68 + tx*4] = acc[i];
    #pragma unroll
    for (int it = 0; it < 16; ++it) {
        int e = tid + it*256;
        int c = e >> 6, k = e & 63;
        s_B[k*68 + c] = gw[e];                 // W0^T
    }
    __syncthreads();

    // HW0 = emb @ W0^T (no bias)
    float4 acc2[4];
    #pragma unroll
    for (int i = 0; i < 4; ++i) acc2[i] = make_float4(0.f,0.f,0.f,0.f);
    #pragma unroll 8
    for (int kk = 0; kk < 64; ++kk) {
        float4 bb = *(const float4*)&s_B[kk*68 + tx*4];
        float a0 = s_A[(ty*4+0)*68 + kk];
        float a1 = s_A[(ty*4+1)*68 + kk];
        float a2 = s_A[(ty*4+2)*68 + kk];
        float a3 = s_A[(ty*4+3)*68 + kk];
        FMA4(acc2[0], a0, bb); FMA4(acc2[1], a1, bb);
        FMA4(acc2[2], a2, bb); FMA4(acc2[3], a3, bb);
    }
    #pragma unroll
    for (int i = 0; i < 4; ++i)
        *(float4*)&g_xw0[p[i]*64 + tx*4] = acc2[i];
}

// ---------------- K2: G' = Nrm^T @ HW per (t,b) + last-block combine -------------
__global__ __launch_bounds__(256) void k_gmat(int l, const float* __restrict__ cont)
{
    const float4* nrm4 = (const float4*)g_nrmP;
    const float4* hw4  = (const float4*)((l == 0) ? g_xw0 : g_xw1);
    __shared__ __align__(16) float s_A [64*68];
    __shared__ __align__(16) float s_Bh[64*68];
    __shared__ float s_S[112];
    __shared__ int s_last;
    int t = blockIdx.x, b = blockIdx.y;
    int tid = threadIdx.x;
    int tx = tid & 15, ty = tid >> 4;

    if (tid < Tt*Tt) s_S[tid] = 1.f / (1.f + expf(-cont[tid]));
    GDC_WAIT(); GDC_LAUNCH();
    int Kt = g_cnt[b*Tt + t];
    int rbase = (b << 10) + g_off[b*Tt + t];
    float4 acc[4];
    #pragma unroll
    for (int i = 0; i < 4; ++i) acc[i] = make_float4(0.f,0.f,0.f,0.f);

    for (int r0 = 0; r0 < Kt; r0 += 64) {
        #pragma unroll
        for (int it = 0; it < 4; ++it) {
            int e = tid + it*256;
            int rr = e >> 4, kq = e & 15;
            int r = r0 + rr;
            float4 a = make_float4(0.f,0.f,0.f,0.f);
            float4 w = make_float4(0.f,0.f,0.f,0.f);
            if (r < Kt) {
                int gi = (rbase + r)*16 + kq;
                a = nrm4[gi];
                w = hw4[gi];
            }
            *(float4*)&s_A [rr*68 + kq*4] = a;
            *(float4*)&s_Bh[rr*68 + kq*4] = w;
        }
        __syncthreads();
        #pragma unroll 8
        for (int rr = 0; rr < 64; ++rr) {
            float4 a  = *(const float4*)&s_A [rr*68 + ty*4];
            float4 bb = *(const float4*)&s_Bh[rr*68 + tx*4];
            FMA4(acc[0], a.x, bb); FMA4(acc[1], a.y, bb);
            FMA4(acc[2], a.z, bb); FMA4(acc[3], a.w, bb);
        }
        __syncthreads();
    }
    float* Gp = &g_G[(b*Tt + t)*4096];
    #pragma unroll
    for (int i = 0; i < 4; ++i)
        *(float4*)&Gp[(ty*4 + i)*64 + tx*4] = acc[i];

    // arrival: last of the 10 blocks for batch b computes M'[b]
    __threadfence();
    __syncthreads();
    if (tid == 0) s_last = atomicAdd(&g_bsync[b], 1);
    __syncthreads();
    if (s_last != Tt - 1) return;
    __threadfence();                       // acquire all 10 G'[b,*]
    if (tid == 0) g_bsync[b] = 0;          // reset for next layer / replay

    const float4* G4 = (const float4*)g_G + (size_t)b*10240;
    float4*       M4 = (float4*)g_M       + (size_t)b*10240;
    #pragma unroll
    for (int it = 0; it < 4; ++it) {
        int i4 = tid + it*256;             // 0..1023 float4 within 64x64
        float4 g[Tt];
        #pragma unroll
        for (int q = 0; q < Tt; ++q) g[q] = G4[q*1024 + i4];
        #pragma unroll
        for (int tp = 0; tp < Tt; ++tp) {
            float4 o = make_float4(0.f,0.f,0.f,0.f);
            #pragma unroll
            for (int q = 0; q < Tt; ++q) {
                float s = s_S[tp*Tt + q];
                FMA4(o, s, g[q]);
            }
            M4[tp*1024 + i4] = o;
        }
    }
}

// ---------------- K3: layer. l=0: h1=relu(HW0+agg+b0), HW1=h1@W1^T --------------
//                        l=1: h2=relu(HW1+agg+b1) -> g_h2P + ctx
__global__ __launch_bounds__(256) void k_layer(
    int l, const float* __restrict__ gnn_w, const float* __restrict__ gnn_b)
{
    const float* hw = (l == 0) ? g_xw0 : g_xw1;
    extern __shared__ __align__(16) float sm[];
    float* s_B  = sm;            // M'  [k][d] stride 68
    float* s_At = sm + 4352;     // nrm^T [k][r] stride 68
    float* s_W  = sm + 8704;     // W1^T [k][c] (l=0)
    float* s_Xt = sm + 13056;    // h1^T [k][r] (l=0)
    __shared__ __align__(16) float s_bias[64];
    __shared__ __align__(16) float s_csum[16][64];

    int t = blockIdx.x, b = blockIdx.y;
    int tid = threadIdx.x;
    int tx = tid & 15, ty = tid >> 4;

    if (tid < 64) s_bias[tid] = gnn_b[l*64 + tid];
    if (l == 0) {
        const float* Wp = gnn_w + 4096;     // W1
        #pragma unroll
        for (int it = 0; it < 16; ++it) {
            int e = tid + it*256;
            s_W[(e & 63)*68 + (e >> 6)] = Wp[e];   // W1^T [k][c]
        }
    }
    GDC_WAIT(); GDC_LAUNCH();
    int Kt = g_cnt[b*Tt + t];
    if (Kt == 0) return;
    int rbase = (b << 10) + g_off[b*Tt + t];

    const float4* Mp4 = (const float4*)&g_M[(b*Tt + t)*4096];
    #pragma unroll
    for (int it = 0; it < 4; ++it) {
        int e = tid + it*256;
        *(float4*)&s_B[(e >> 4)*68 + (e & 15)*4] = Mp4[e];   // natural [k][d]
    }
    float4 psum = make_float4(0.f,0.f,0.f,0.f);
    float4 bias = *(const float4*)&s_bias[tx*4];
    __syncthreads();

    for (int r0 = 0; r0 < Kt; r0 += 64) {
        #pragma unroll
        for (int it = 0; it < 16; ++it) {
            int e = tid + it*256;
            int rr = e >> 6, k = e & 63;
            int r = r0 + rr;
            s_At[k*68 + rr] = (r < Kt) ? g_nrmP[(rbase + r)*64 + k] : 0.f;
        }
        __syncthreads();

        // GEMM1: agg[r][d] = sum_k nrm[r][k] M'[k][d]
        float4 acc[4];
        #pragma unroll
        for (int i = 0; i < 4; ++i) acc[i] = make_float4(0.f,0.f,0.f,0.f);
        #pragma unroll 8
        for (int kk = 0; kk < 64; ++kk) {
            float4 a  = *(const float4*)&s_At[kk*68 + ty*4];
            float4 bb = *(const float4*)&s_B [kk*68 + tx*4];
            FMA4(acc[0], a.x, bb); FMA4(acc[1], a.y, bb);
            FMA4(acc[2], a.z, bb); FMA4(acc[3], a.w, bb);
        }

        if (l == 0) {
            // h1 = relu(HW0 + agg + b0), store transposed
            #pragma unroll
            for (int i = 0; i < 4; ++i) {
                int r = r0 + ty*4 + i;
                float4 x = acc[i];
                if (r < Kt) {
                    float4 hv = *(const float4*)&hw[(rbase + r)*64 + tx*4];
                    x.x = fmaxf(x.x + hv.x + bias.x, 0.f);
                    x.y = fmaxf(x.y + hv.y + bias.y, 0.f);
                    x.z = fmaxf(x.z + hv.z + bias.z, 0.f);
                    x.w = fmaxf(x.w + hv.w + bias.w, 0.f);
                } else {
                    x = make_float4(0.f,0.f,0.f,0.f);
                }
                s_Xt[(tx*4+0)*68 + ty*4 + i] = x.x;
                s_Xt[(tx*4+1)*68 + ty*4 + i] = x.y;
                s_Xt[(tx*4+2)*68 + ty*4 + i] = x.z;
                s_Xt[(tx*4+3)*68 + ty*4 + i] = x.w;
            }
            __syncthreads();

            // GEMM2: HW1[r][c] = sum_k h1[r][k] W1[c][k]
            float4 acc2[4];
            #pragma unroll
            for (int i = 0; i < 4; ++i) acc2[i] = make_float4(0.f,0.f,0.f,0.f);
            #pragma unroll 8
            for (int kk = 0; kk < 64; ++kk) {
                float4 a  = *(const float4*)&s_Xt[kk*68 + ty*4];
                float4 bb = *(const float4*)&s_W [kk*68 + tx*4];
                FMA4(acc2[0], a.x, bb); FMA4(acc2[1], a.y, bb);
                FMA4(acc2[2], a.z, bb); FMA4(acc2[3], a.w, bb);
            }
            #pragma unroll
            for (int i = 0; i < 4; ++i) {
                int r = r0 + ty*4 + i;
                if (r < Kt)
                    *(float4*)&g_xw1[(rbase + r)*64 + tx*4] = acc2[i];
            }
            __syncthreads();
        } else {
            // h2 = relu(HW1 + agg + b1)
            #pragma unroll
            for (int i = 0; i < 4; ++i) {
                int r = r0 + ty*4 + i;
                if (r < Kt) {
                    float4 x = acc[i];
                    float4 hv = *(const float4*)&hw[(rbase + r)*64 + tx*4];
                    x.x = fmaxf(x.x + hv.x + bias.x, 0.f);
                    x.y = fmaxf(x.y + hv.y + bias.y, 0.f);
                    x.z = fmaxf(x.z + hv.z + bias.z, 0.f);
                    x.w = fmaxf(x.w + hv.w + bias.w, 0.f);
                    *(float4*)&g_h2P[(rbase + r)*64 + tx*4] = x;
                    psum.x += x.x; psum.y += x.y; psum.z += x.z; psum.w += x.w;
                }
            }
            __syncthreads();
        }
    }

    if (l == 1) {
        *(float4*)&s_csum[ty][tx*4] = psum;
        __syncthreads();
        if (tid < 64) {
            float s = 0.f;
            #pragma unroll
            for (int q = 0; q < 16; ++q) s += s_csum[q][tid];
            atomicAdd(&g_ctx[b*64 + tid], s);
        }
    }
}

// ---------------- K4: head (+GRU per block, K=64, gathers h2P via pos) ----------
__global__ __launch_bounds__(256) void k_head(
    const float* __restrict__ prev, const float* __restrict__ wih,
    const float* __restrict__ whh,  const float* __restrict__ bih,
    const float* __restrict__ bhh,
    const float* __restrict__ w1, const float* __restrict__ b1,
    const float* __restrict__ w2, const float* __restrict__ b2,
    float* __restrict__ out)
{
    __shared__ __align__(16) float s_X[64*68];
    __shared__ __align__(16) float s_W[64*68];
    __shared__ __align__(16) float s_g[320];
    __shared__ __align__(16) float s_hs[64];
    __shared__ __align__(16) float s_w2[64];
    __shared__ int s_pos[64];
    int tid = threadIdx.x;
    int tx = tid & 15, ty = tid >> 4;
    int u = blockIdx.x;
    int base = u << 6;
    int b = u >> 4;

    #pragma unroll
    for (int it = 0; it < 16; ++it) {
        int e = tid + it*256;
        int j = e >> 6, k = e & 63;
        s_W[k*68 + j] = w1[j*96 + k];
    }
    if (tid < 64) s_w2[tid] = w2[tid];
    GDC_WAIT();
    if (tid < 64)       s_g[tid] = g_ctx[b*64 + tid] * (1.f/1024.f);
    else if (tid < 96)  s_g[tid] = prev[b*32 + (tid - 64)];
    else if (tid < 160) s_pos[tid - 96] = g_pos[base + (tid - 96)];
    __syncthreads();

    const float4* h24 = (const float4*)g_h2P;
    #pragma unroll
    for (int it = 0; it < 4; ++it) {
        int e = tid + it*256;
        int rr = e >> 4, kq = e & 15;
        *(float4*)&s_X[rr*68 + kq*4] = h24[s_pos[rr]*16 + kq];
    }
    if (tid < 96) {
        float gi = bih[tid], gh = bhh[tid];
        #pragma unroll 16
        for (int k = 0; k < 64; ++k) gi += s_g[k] * wih[tid*64 + k];
        #pragma unroll 16
        for (int k = 0; k < 32; ++k) gh += s_g[64 + k] * whh[tid*32 + k];
        s_g[96 + tid] = gi; s_g[192 + tid] = gh;
    }
    __syncthreads();
    if (tid < 32) {
        float r  = 1.f / (1.f + expf(-(s_g[96  + tid] + s_g[192 + tid])));
        float z  = 1.f / (1.f + expf(-(s_g[128 + tid] + s_g[224 + tid])));
        float nn = tanhf(s_g[160 + tid] + r * s_g[256 + tid]);
        float ns = (1.f - z)*nn + z*s_g[64 + tid];
        s_g[288 + tid] = ns;
        if ((u & 15) == 0) out[Bb*Nn + b*32 + tid] = ns;
    }
    __syncthreads();
    if (tid < 64) {
        float v = b1[tid];
        #pragma unroll
        for (int k = 0; k < 32; ++k) v += w1[tid*96 + 64 + k] * s_g[288 + k];
        s_hs[tid] = v;
    }
    __syncthreads();

    float4 hs = *(const float4*)&s_hs[tx*4];
    float4 acc[4] = {hs, hs, hs, hs};
    #pragma unroll 8
    for (int kk = 0; kk < 64; ++kk) {
        float4 bb = *(const float4*)&s_W[kk*68 + tx*4];
        float a0 = s_X[(ty*4+0)*68 + kk];
        float a1 = s_X[(ty*4+1)*68 + kk];
        float a2 = s_X[(ty*4+2)*68 + kk];
        float a3 = s_X[(ty*4+3)*68 + kk];
        FMA4(acc[0], a0, bb); FMA4(acc[1], a1, bb);
        FMA4(acc[2], a2, bb); FMA4(acc[3], a3, bb);
    }
    float4 w2v = *(const float4*)&s_w2[tx*4];
    float b2v = b2[0];
    #pragma unroll
    for (int i = 0; i < 4; ++i) {
        float y = fmaxf(acc[i].x, 0.f)*w2v.x + fmaxf(acc[i].y, 0.f)*w2v.y
                + fmaxf(acc[i].z, 0.f)*w2v.z + fmaxf(acc[i].w, 0.f)*w2v.w;
        #pragma unroll
        for (int o = 8; o > 0; o >>= 1) y += __shfl_xor_sync(0xffffffffu, y, o);
        if (tx == 0) out[base + ty*4 + i] = y + b2v;
    }
}

// ---------------- launch ---------------------------------------------------------
extern "C" void kernel_launch(void* const* d_in, const int* in_sizes, int n_in,
                              void* d_out, int out_size)
{
    const float* tf    = (const float*)d_in[0];
    const int*   types = (const int*)  d_in[1];
    const float* prev  = (const float*)d_in[2];
    const float* ew1   = (const float*)d_in[3];
    const float* eb1   = (const float*)d_in[4];
    const float* ew2   = (const float*)d_in[5];
    const float* eb2   = (const float*)d_in[6];
    const float* cont  = (const float*)d_in[7];
    const float* gw    = (const float*)d_in[8];
    const float* gb    = (const float*)d_in[9];
    const float* wih   = (const float*)d_in[10];
    const float* whh   = (const float*)d_in[11];
    const float* bih   = (const float*)d_in[12];
    const float* bhh   = (const float*)d_in[13];
    const float* hw1   = (const float*)d_in[14];
    const float* hb1   = (const float*)d_in[15];
    const float* hw2   = (const float*)d_in[16];
    const float* hb2   = (const float*)d_in[17];
    float* out = (float*)d_out;

    cudaFuncSetAttribute(k_layer, cudaFuncAttributeMaxDynamicSharedMemorySize, 69632);

    cudaLaunchAttribute at;
    at.id = cudaLaunchAttributeProgrammaticStreamSerialization;
    at.val.programmaticStreamSerializationAllowed = 1;
    cudaLaunchConfig_t cfg = {};
    cfg.attrs = &at;
    cfg.numAttrs = 1;
    cfg.stream = 0;

    k_bucket<<<Bb, 1024>>>(types);

    cfg.gridDim = dim3(1024); cfg.blockDim = dim3(256); cfg.dynamicSmemBytes = 0;
    cudaLaunchKernelEx(&cfg, k_enc, tf, ew1, eb1, ew2, eb2, gw);

    for (int l = 0; l < 2; ++l) {
        cfg.gridDim = dim3(Tt, Bb); cfg.blockDim = dim3(256); cfg.dynamicSmemBytes = 0;
        cudaLaunchKernelEx(&cfg, k_gmat, l, cont);
        cfg.gridDim = dim3(Tt, Bb); cfg.blockDim = dim3(256);
        cfg.dynamicSmemBytes = (l == 0) ? 69632 : 34816;
        cudaLaunchKernelEx(&cfg, k_layer, l, gw, gb);
    }
    cfg.gridDim = dim3(1024); cfg.blockDim = dim3(256); cfg.dynamicSmemBytes = 0;
    cudaLaunchKernelEx(&cfg, k_head, prev, wih, whh, bih, bhh,
                       hw1, hb1, hw2, hb2, out);
}

// round 16
// speedup vs baseline: 1.1360x; 1.1360x over previous
#include <cuda_runtime.h>
#include <math.h>

#define Bb 64
#define Nn 1024
#define Hh 64
#define Tt 10

// ---------------- scratch (device globals; permuted row space) -----------------
__device__ __align__(16) float g_nrmP[Bb*Nn*Hh];   // emb/||emb||, bucket order
__device__ __align__(16) float g_xw0 [Bb*Nn*Hh];   // emb @ W0^T
__device__ __align__(16) float g_xw1 [Bb*Nn*Hh];   // h1  @ W1^T
__device__ __align__(16) float g_h2P [Bb*Nn*Hh];
__device__ __align__(16) float g_G   [Bb*Tt*Hh*Hh];
__device__ __align__(16) float g_M   [Bb*Tt*Hh*Hh];
__device__ int g_pos[Bb*Nn];
__device__ int g_off[Bb*Tt];
__device__ int g_cnt[Bb*Tt];
__device__ __align__(16) float g_ctx[Bb*Hh];

#define FMA4(A, s, v) { (A).x += (s)*(v).x; (A).y += (s)*(v).y; (A).z += (s)*(v).z; (A).w += (s)*(v).w; }
#define GDC_WAIT()   asm volatile("griddepcontrol.wait;" ::: "memory")
#define GDC_LAUNCH() asm volatile("griddepcontrol.launch_dependents;" ::: "memory")

// cp.async helpers
__device__ __forceinline__ unsigned sm32(const void* p) {
    unsigned a;
    asm("{ .reg .u64 t; cvta.to.shared.u64 t, %1; cvt.u32.u64 %0, t; }"
        : "=r"(a) : "l"(p));
    return a;
}
__device__ __forceinline__ void cpa16(unsigned dst, const void* src, int sz) {
    asm volatile("cp.async.ca.shared.global [%0], [%1], 16, %2;"
                 :: "r"(dst), "l"(src), "r"(sz));
}
#define CP_COMMIT() asm volatile("cp.async.commit_group;" ::: "memory")
#define CP_WAIT1()  asm volatile("cp.async.wait_group 1;" ::: "memory")

// ---------------- K0: bucket ----------------------------------------------------
__global__ __launch_bounds__(1024) void k_bucket(const int* __restrict__ types)
{
    __shared__ int s_cnt[16];
    __shared__ int s_off[16];
    int b = blockIdx.x, n = threadIdx.x;
    if (n < Tt) s_cnt[n] = 0;
    if (n < 64) g_ctx[b*64 + n] = 0.f;
    __syncthreads();
    int t = types[b*Nn + n];
    int rank = atomicAdd(&s_cnt[t], 1);
    __syncthreads();
    if (n == 0) {
        int a = 0;
        #pragma unroll
        for (int i = 0; i < Tt; ++i) { s_off[i] = a; a += s_cnt[i]; }
    }
    __syncthreads();
    g_pos[b*Nn + n] = b*Nn + s_off[t] + rank;
    if (n < Tt) { g_cnt[b*Tt + n] = s_cnt[n]; g_off[b*Tt + n] = s_off[n]; }
    GDC_LAUNCH();
}

// ---------------- K1: encoder -> nrmP + HW0 = emb @ W0^T ------------------------
__global__ __launch_bounds__(256) void k_enc(
    const float* __restrict__ tf,
    const float* __restrict__ w1, const float* __restrict__ b1,
    const float* __restrict__ w2, const float* __restrict__ b2,
    const float* __restrict__ gw)
{
    __shared__ __align__(16) float s_A[64*68];
    __shared__ __align__(16) float s_B[64*68];
    __shared__ __align__(16) float s_f[192];
    __shared__ __align__(16) float s_w1[192];
    __shared__ __align__(16) float s_b1[64];
    __shared__ __align__(16) float s_b2[64];
    int tid = threadIdx.x;
    int tx = tid & 15, ty = tid >> 4;
    int base = blockIdx.x * 64;

    #pragma unroll
    for (int it = 0; it < 16; ++it) {
        int e = tid + it*256;
        int j = e >> 6, k = e & 63;
        s_B[k*68 + j] = w2[e];                 // w2^T
    }
    if (tid < 192) { s_f[tid] = tf[base*3 + tid]; s_w1[tid] = w1[tid]; }
    if (tid < 64)  { s_b1[tid] = b1[tid]; s_b2[tid] = b2[tid]; }
    __syncthreads();
    GDC_LAUNCH();

    #pragma unroll
    for (int it = 0; it < 16; ++it) {
        int e = tid + it*256;
        int row = e >> 6, k = e & 63;
        float h = s_f[row*3+0]*s_w1[k*3+0] + s_f[row*3+1]*s_w1[k*3+1]
                + s_f[row*3+2]*s_w1[k*3+2] + s_b1[k];
        s_A[row*68 + k] = fmaxf(h, 0.f);
    }
    __syncthreads();

    // emb = h1 @ w2^T + b2
    float4 acc[4];
    #pragma unroll
    for (int i = 0; i < 4; ++i) acc[i] = make_float4(0.f,0.f,0.f,0.f);
    #pragma unroll 8
    for (int kk = 0; kk < 64; ++kk) {
        float4 bb = *(const float4*)&s_B[kk*68 + tx*4];
        float a0 = s_A[(ty*4+0)*68 + kk];
        float a1 = s_A[(ty*4+1)*68 + kk];
        float a2 = s_A[(ty*4+2)*68 + kk];
        float a3 = s_A[(ty*4+3)*68 + kk];
        FMA4(acc[0], a0, bb); FMA4(acc[1], a1, bb);
        FMA4(acc[2], a2, bb); FMA4(acc[3], a3, bb);
    }
    float4 bias = *(const float4*)&s_b2[tx*4];
    GDC_WAIT();
    int p[4];
    #pragma unroll
    for (int i = 0; i < 4; ++i) {
        acc[i].x += bias.x; acc[i].y += bias.y;
        acc[i].z += bias.z; acc[i].w += bias.w;
        float sq = acc[i].x*acc[i].x + acc[i].y*acc[i].y
                 + acc[i].z*acc[i].z + acc[i].w*acc[i].w;
        #pragma unroll
        for (int o = 8; o > 0; o >>= 1) sq += __shfl_xor_sync(0xffffffffu, sq, o);
        float inv = 1.f / fmaxf(sqrtf(sq), 1e-12f);
        p[i] = g_pos[base + ty*4 + i];
        float4 nv = make_float4(acc[i].x*inv, acc[i].y*inv, acc[i].z*inv, acc[i].w*inv);
        *(float4*)&g_nrmP[p[i]*64 + tx*4] = nv;
    }
    __syncthreads();

    #pragma unroll
    for (int i = 0; i < 4; ++i)
        *(float4*)&s_A[(ty*4+i)*68 + tx*4] = acc[i];
    #pragma unroll
    for (int it = 0; it < 16; ++it) {
        int e = tid + it*256;
        int c = e >> 6, k = e & 63;
        s_B[k*68 + c] = gw[e];                 // W0^T
    }
    __syncthreads();

    // HW0 = emb @ W0^T (no bias)
    float4 acc2[4];
    #pragma unroll
    for (int i = 0; i < 4; ++i) acc2[i] = make_float4(0.f,0.f,0.f,0.f);
    #pragma unroll 8
    for (int kk = 0; kk < 64; ++kk) {
        float4 bb = *(const float4*)&s_B[kk*68 + tx*4];
        float a0 = s_A[(ty*4+0)*68 + kk];
        float a1 = s_A[(ty*4+1)*68 + kk];
        float a2 = s_A[(ty*4+2)*68 + kk];
        float a3 = s_A[(ty*4+3)*68 + kk];
        FMA4(acc2[0], a0, bb); FMA4(acc2[1], a1, bb);
        FMA4(acc2[2], a2, bb); FMA4(acc2[3], a3, bb);
    }
    #pragma unroll
    for (int i = 0; i < 4; ++i)
        *(float4*)&g_xw0[p[i]*64 + tx*4] = acc2[i];
}

// ---------------- K2: G' = Nrm^T @ HW per (t,b), cp.async double-buffered -------
// dyn smem: A0 | A1 | B0 | B1, each 4352 floats = 69632 B
__global__ __launch_bounds__(256) void k_gmat(int l)
{
    const float4* nrm4 = (const float4*)g_nrmP;
    const float4* hw4  = (const float4*)((l == 0) ? g_xw0 : g_xw1);
    extern __shared__ __align__(16) float sm[];
    int t = blockIdx.x, b = blockIdx.y;
    int tid = threadIdx.x;
    int tx = tid & 15, ty = tid >> 4;
    unsigned smb = sm32(sm);

    GDC_WAIT(); GDC_LAUNCH();
    int Kt = g_cnt[b*Tt + t];
    int rbase = (b << 10) + g_off[b*Tt + t];

    // prologue: prefetch tile 0 into buf 0
    #pragma unroll
    for (int it = 0; it < 4; ++it) {
        int e = tid + it*256;
        int rr = e >> 4, kq = e & 15;
        int r = rr;                            // r0 = 0
        int sz = (r < Kt) ? 16 : 0;
        int gi = (rbase + ((r < Kt) ? r : 0))*16 + kq;
        cpa16(smb + (0    + rr*68 + kq*4)*4, nrm4 + gi, sz);
        cpa16(smb + (8704 + rr*68 + kq*4)*4, hw4  + gi, sz);
    }
    CP_COMMIT();

    float4 acc[4];
    #pragma unroll
    for (int i = 0; i < 4; ++i) acc[i] = make_float4(0.f,0.f,0.f,0.f);

    int nt = (Kt + 63) >> 6;
    for (int i = 0; i < nt; ++i) {
        int cur = i & 1, nxt = cur ^ 1;
        // issue prefetch of tile i+1
        if (i + 1 < nt) {
            int r1 = (i + 1) << 6;
            #pragma unroll
            for (int it = 0; it < 4; ++it) {
                int e = tid + it*256;
                int rr = e >> 4, kq = e & 15;
                int r = r1 + rr;
                int sz = (r < Kt) ? 16 : 0;
                int gi = (rbase + ((r < Kt) ? r : 0))*16 + kq;
                cpa16(smb + (nxt*4352        + rr*68 + kq*4)*4, nrm4 + gi, sz);
                cpa16(smb + (8704 + nxt*4352 + rr*68 + kq*4)*4, hw4  + gi, sz);
            }
        }
        CP_COMMIT();
        CP_WAIT1();                // tile i complete (groups finish in order)
        __syncthreads();

        const float* sA = sm + cur*4352;
        const float* sB = sm + 8704 + cur*4352;
        #pragma unroll 8
        for (int rr = 0; rr < 64; ++rr) {
            float4 a  = *(const float4*)&sA[rr*68 + ty*4];
            float4 bb = *(const float4*)&sB[rr*68 + tx*4];
            FMA4(acc[0], a.x, bb); FMA4(acc[1], a.y, bb);
            FMA4(acc[2], a.z, bb); FMA4(acc[3], a.w, bb);
        }
        __syncthreads();           // protect cur from prefetch at i+2
    }
    float* Gp = &g_G[(b*Tt + t)*4096];
    #pragma unroll
    for (int i = 0; i < 4; ++i)
        *(float4*)&Gp[(ty*4 + i)*64 + tx*4] = acc[i];
}

// ---------------- K2b: M' = sum_t sigmoid(C) G' ---------------------------------
__global__ __launch_bounds__(128) void k_combine(const float* __restrict__ cont)
{
    __shared__ float s_S[Tt*Tt];
    int b = blockIdx.x, tid = threadIdx.x;
    if (tid < Tt*Tt) s_S[tid] = 1.f / (1.f + expf(-cont[tid]));
    __syncthreads();
    GDC_WAIT(); GDC_LAUNCH();
    int i4 = blockIdx.y * 128 + tid;
    const float4* G4 = (const float4*)g_G + (size_t)b*10240;
    float4*       M4 = (float4*)g_M       + (size_t)b*10240;
    float4 g[Tt];
    #pragma unroll
    for (int t = 0; t < Tt; ++t) g[t] = G4[t*1024 + i4];
    #pragma unroll
    for (int tp = 0; tp < Tt; ++tp) {
        float4 o = make_float4(0.f,0.f,0.f,0.f);
        #pragma unroll
        for (int t = 0; t < Tt; ++t) {
            float s = s_S[tp*Tt + t];
            FMA4(o, s, g[t]);
        }
        M4[tp*1024 + i4] = o;
    }
}

// ---------------- K3: layer (cp.async double-buffered A; natural X) -------------
// l=0: h1 = relu(HW0+agg+b0); HW1 = h1 @ W1^T.  smem: SB|SW|SA0|SA1 = 69632
// l=1: h2 = relu(HW1+agg+b1) -> g_h2P + ctx.    smem: SB|SA0|SA1    = 52224
__global__ __launch_bounds__(256) void k_layer(
    int l, const float* __restrict__ gnn_w, const float* __restrict__ gnn_b)
{
    const float* hw = (l == 0) ? g_xw0 : g_xw1;
    const float4* nrm4 = (const float4*)g_nrmP;
    extern __shared__ __align__(16) float sm[];
    float* s_B = sm;                                  // M' [k][d] stride 68
    float* s_W = (l == 0) ? sm + 4352 : (float*)0;    // W1^T [k][c] (l=0)
    int aoff = (l == 0) ? 8704 : 4352;                // SA0 offset (floats)
    __shared__ __align__(16) float s_bias[64];
    __shared__ __align__(16) float s_csum[16][64];

    int t = blockIdx.x, b = blockIdx.y;
    int tid = threadIdx.x;
    int tx = tid & 15, ty = tid >> 4;
    unsigned smb = sm32(sm);

    if (tid < 64) s_bias[tid] = gnn_b[l*64 + tid];
    if (l == 0) {
        const float* Wp = gnn_w + 4096;     // W1
        #pragma unroll
        for (int it = 0; it < 16; ++it) {
            int e = tid + it*256;
            s_W[(e & 63)*68 + (e >> 6)] = Wp[e];   // W1^T [k][c]
        }
    }
    GDC_WAIT(); GDC_LAUNCH();
    int Kt = g_cnt[b*Tt + t];
    if (Kt == 0) return;
    int rbase = (b << 10) + g_off[b*Tt + t];

    // prologue: prefetch nrm tile 0 into SA0
    #pragma unroll
    for (int it = 0; it < 4; ++it) {
        int e = tid + it*256;
        int rr = e >> 4, kq = e & 15;
        int sz = (rr < Kt) ? 16 : 0;
        int gi = (rbase + ((rr < Kt) ? rr : 0))*16 + kq;
        cpa16(smb + (aoff + rr*68 + kq*4)*4, nrm4 + gi, sz);
    }
    CP_COMMIT();

    const float4* Mp4 = (const float4*)&g_M[(b*Tt + t)*4096];
    #pragma unroll
    for (int it = 0; it < 4; ++it) {
        int e = tid + it*256;
        *(float4*)&s_B[(e >> 4)*68 + (e & 15)*4] = Mp4[e];   // natural [k][d]
    }
    float4 psum = make_float4(0.f,0.f,0.f,0.f);
    float4 bias = *(const float4*)&s_bias[tx*4];

    int nt = (Kt + 63) >> 6;
    for (int i = 0; i < nt; ++i) {
        int cur = i & 1, nxt = cur ^ 1;
        int r0 = i << 6;
        if (i + 1 < nt) {
            int r1 = r0 + 64;
            #pragma unroll
            for (int it = 0; it < 4; ++it) {
                int e = tid + it*256;
                int rr = e >> 4, kq = e & 15;
                int r = r1 + rr;
                int sz = (r < Kt) ? 16 : 0;
                int gi = (rbase + ((r < Kt) ? r : 0))*16 + kq;
                cpa16(smb + (aoff + nxt*4352 + rr*68 + kq*4)*4, nrm4 + gi, sz);
            }
        }
        CP_COMMIT();
        CP_WAIT1();
        __syncthreads();

        float* sA = sm + aoff + cur*4352;

        // GEMM1: agg[r][d] = sum_k nrm[r][k] M'[k][d]  (scalar-broadcast A)
        float4 acc[4];
        #pragma unroll
        for (int i2 = 0; i2 < 4; ++i2) acc[i2] = make_float4(0.f,0.f,0.f,0.f);
        #pragma unroll 8
        for (int kk = 0; kk < 64; ++kk) {
            float4 bb = *(const float4*)&s_B[kk*68 + tx*4];
            float a0 = sA[(ty*4+0)*68 + kk];
            float a1 = sA[(ty*4+1)*68 + kk];
            float a2 = sA[(ty*4+2)*68 + kk];
            float a3 = sA[(ty*4+3)*68 + kk];
            FMA4(acc[0], a0, bb); FMA4(acc[1], a1, bb);
            FMA4(acc[2], a2, bb); FMA4(acc[3], a3, bb);
        }

        if (l == 0) {
            // X = relu(HW0 + agg + b0) in regs
            float4 x[4];
            #pragma unroll
            for (int i2 = 0; i2 < 4; ++i2) {
                int r = r0 + ty*4 + i2;
                x[i2] = acc[i2];
                if (r < Kt) {
                    float4 hv = *(const float4*)&hw[(rbase + r)*64 + tx*4];
                    x[i2].x = fmaxf(x[i2].x + hv.x + bias.x, 0.f);
                    x[i2].y = fmaxf(x[i2].y + hv.y + bias.y, 0.f);
                    x[i2].z = fmaxf(x[i2].z + hv.z + bias.z, 0.f);
                    x[i2].w = fmaxf(x[i2].w + hv.w + bias.w, 0.f);
                } else {
                    x[i2] = make_float4(0.f,0.f,0.f,0.f);
                }
            }
            __syncthreads();       // GEMM1 reads of sA done
            #pragma unroll
            for (int i2 = 0; i2 < 4; ++i2)
                *(float4*)&sA[(ty*4+i2)*68 + tx*4] = x[i2];   // natural layout
            __syncthreads();

            // GEMM2: HW1[r][c] = sum_k h1[r][k] W1[c][k]  (scalar-broadcast A)
            float4 acc2[4];
            #pragma unroll
            for (int i2 = 0; i2 < 4; ++i2) acc2[i2] = make_float4(0.f,0.f,0.f,0.f);
            #pragma unroll 8
            for (int kk = 0; kk < 64; ++kk) {
                float4 bb = *(const float4*)&s_W[kk*68 + tx*4];
                float a0 = sA[(ty*4+0)*68 + kk];
                float a1 = sA[(ty*4+1)*68 + kk];
                float a2 = sA[(ty*4+2)*68 + kk];
                float a3 = sA[(ty*4+3)*68 + kk];
                FMA4(acc2[0], a0, bb); FMA4(acc2[1], a1, bb);
                FMA4(acc2[2], a2, bb); FMA4(acc2[3], a3, bb);
            }
            #pragma unroll
            for (int i2 = 0; i2 < 4; ++i2) {
                int r = r0 + ty*4 + i2;
                if (r < Kt)
                    *(float4*)&g_xw1[(rbase + r)*64 + tx*4] = acc2[i2];
            }
            __syncthreads();       // protect sA (X) before prefetch at i+1
        } else {
            // h2 = relu(HW1 + agg + b1)
            #pragma unroll
            for (int i2 = 0; i2 < 4; ++i2) {
                int r = r0 + ty*4 + i2;
                if (r < Kt) {
                    float4 x = acc[i2];
                    float4 hv = *(const float4*)&hw[(rbase + r)*64 + tx*4];
                    x.x = fmaxf(x.x + hv.x + bias.x, 0.f);
                    x.y = fmaxf(x.y + hv.y + bias.y, 0.f);
                    x.z = fmaxf(x.z + hv.z + bias.z, 0.f);
                    x.w = fmaxf(x.w + hv.w + bias.w, 0.f);
                    *(float4*)&g_h2P[(rbase + r)*64 + tx*4] = x;
                    psum.x += x.x; psum.y += x.y; psum.z += x.z; psum.w += x.w;
                }
            }
            __syncthreads();
        }
    }

    if (l == 1) {
        *(float4*)&s_csum[ty][tx*4] = psum;
        __syncthreads();
        if (tid < 64) {
            float s = 0.f;
            #pragma unroll
            for (int q = 0; q < 16; ++q) s += s_csum[q][tid];
            atomicAdd(&g_ctx[b*64 + tid], s);
        }
    }
}

// ---------------- K4: head (+GRU per block, K=64, gathers h2P via pos) ----------
__global__ __launch_bounds__(256) void k_head(
    const float* __restrict__ prev, const float* __restrict__ wih,
    const float* __restrict__ whh,  const float* __restrict__ bih,
    const float* __restrict__ bhh,
    const float* __restrict__ w1, const float* __restrict__ b1,
    const float* __restrict__ w2, const float* __restrict__ b2,
    float* __restrict__ out)
{
    __shared__ __align__(16) float s_X[64*68];
    __shared__ __align__(16) float s_W[64*68];
    __shared__ __align__(16) float s_g[320];
    __shared__ __align__(16) float s_hs[64];
    __shared__ __align__(16) float s_w2[64];
    __shared__ int s_pos[64];
    int tid = threadIdx.x;
    int tx = tid & 15, ty = tid >> 4;
    int u = blockIdx.x;
    int base = u << 6;
    int b = u >> 4;

    #pragma unroll
    for (int it = 0; it < 16; ++it) {
        int e = tid + it*256;
        int j = e >> 6, k = e & 63;
        s_W[k*68 + j] = w1[j*96 + k];
    }
    if (tid < 64) s_w2[tid] = w2[tid];
    GDC_WAIT();
    if (tid < 64)       s_g[tid] = g_ctx[b*64 + tid] * (1.f/1024.f);
    else if (tid < 96)  s_g[tid] = prev[b*32 + (tid - 64)];
    else if (tid < 160) s_pos[tid - 96] = g_pos[base + (tid - 96)];
    __syncthreads();

    const float4* h24 = (const float4*)g_h2P;
    #pragma unroll
    for (int it = 0; it < 4; ++it) {
        int e = tid + it*256;
        int rr = e >> 4, kq = e & 15;
        *(float4*)&s_X[rr*68 + kq*4] = h24[s_pos[rr]*16 + kq];
    }
    if (tid < 96) {
        float gi = bih[tid], gh = bhh[tid];
        #pragma unroll 16
        for (int k = 0; k < 64; ++k) gi += s_g[k] * wih[tid*64 + k];
        #pragma unroll 16
        for (int k = 0; k < 32; ++k) gh += s_g[64 + k] * whh[tid*32 + k];
        s_g[96 + tid] = gi; s_g[192 + tid] = gh;
    }
    __syncthreads();
    if (tid < 32) {
        float r  = 1.f / (1.f + expf(-(s_g[96  + tid] + s_g[192 + tid])));
        float z  = 1.f / (1.f + expf(-(s_g[128 + tid] + s_g[224 + tid])));
        float nn = tanhf(s_g[160 + tid] + r * s_g[256 + tid]);
        float ns = (1.f - z)*nn + z*s_g[64 + tid];
        s_g[288 + tid] = ns;
        if ((u & 15) == 0) out[Bb*Nn + b*32 + tid] = ns;
    }
    __syncthreads();
    if (tid < 64) {
        float v = b1[tid];
        #pragma unroll
        for (int k = 0; k < 32; ++k) v += w1[tid*96 + 64 + k] * s_g[288 + k];
        s_hs[tid] = v;
    }
    __syncthreads();

    float4 hs = *(const float4*)&s_hs[tx*4];
    float4 acc[4] = {hs, hs, hs, hs};
    #pragma unroll 8
    for (int kk = 0; kk < 64; ++kk) {
        float4 bb = *(const float4*)&s_W[kk*68 + tx*4];
        float a0 = s_X[(ty*4+0)*68 + kk];
        float a1 = s_X[(ty*4+1)*68 + kk];
        float a2 = s_X[(ty*4+2)*68 + kk];
        float a3 = s_X[(ty*4+3)*68 + kk];
        FMA4(acc[0], a0, bb); FMA4(acc[1], a1, bb);
        FMA4(acc[2], a2, bb); FMA4(acc[3], a3, bb);
    }
    float4 w2v = *(const float4*)&s_w2[tx*4];
    float b2v = b2[0];
    #pragma unroll
    for (int i = 0; i < 4; ++i) {
        float y = fmaxf(acc[i].x, 0.f)*w2v.x + fmaxf(acc[i].y, 0.f)*w2v.y
                + fmaxf(acc[i].z, 0.f)*w2v.z + fmaxf(acc[i].w, 0.f)*w2v.w;
        #pragma unroll
        for (int o = 8; o > 0; o >>= 1) y += __shfl_xor_sync(0xffffffffu, y, o);
        if (tx == 0) out[base + ty*4 + i] = y + b2v;
    }
}

// ---------------- launch ---------------------------------------------------------
extern "C" void kernel_launch(void* const* d_in, const int* in_sizes, int n_in,
                              void* d_out, int out_size)
{
    const float* tf    = (const float*)d_in[0];
    const int*   types = (const int*)  d_in[1];
    const float* prev  = (const float*)d_in[2];
    const float* ew1   = (const float*)d_in[3];
    const float* eb1   = (const float*)d_in[4];
    const float* ew2   = (const float*)d_in[5];
    const float* eb2   = (const float*)d_in[6];
    const float* cont  = (const float*)d_in[7];
    const float* gw    = (const float*)d_in[8];
    const float* gb    = (const float*)d_in[9];
    const float* wih   = (const float*)d_in[10];
    const float* whh   = (const float*)d_in[11];
    const float* bih   = (const float*)d_in[12];
    const float* bhh   = (const float*)d_in[13];
    const float* hw1   = (const float*)d_in[14];
    const float* hb1   = (const float*)d_in[15];
    const float* hw2   = (const float*)d_in[16];
    const float* hb2   = (const float*)d_in[17];
    float* out = (float*)d_out;

    cudaFuncSetAttribute(k_gmat,  cudaFuncAttributeMaxDynamicSharedMemorySize, 69632);
    cudaFuncSetAttribute(k_layer, cudaFuncAttributeMaxDynamicSharedMemorySize, 69632);

    cudaLaunchAttribute at;
    at.id = cudaLaunchAttributeProgrammaticStreamSerialization;
    at.val.programmaticStreamSerializationAllowed = 1;
    cudaLaunchConfig_t cfg = {};
    cfg.attrs = &at;
    cfg.numAttrs = 1;
    cfg.stream = 0;

    k_bucket<<<Bb, 1024>>>(types);

    cfg.gridDim = dim3(1024); cfg.blockDim = dim3(256); cfg.dynamicSmemBytes = 0;
    cudaLaunchKernelEx(&cfg, k_enc, tf, ew1, eb1, ew2, eb2, gw);

    for (int l = 0; l < 2; ++l) {
        cfg.gridDim = dim3(Tt, Bb); cfg.blockDim = dim3(256); cfg.dynamicSmemBytes = 69632;
        cudaLaunchKernelEx(&cfg, k_gmat, l);
        cfg.gridDim = dim3(Bb, 8); cfg.blockDim = dim3(128); cfg.dynamicSmemBytes = 0;
        cudaLaunchKernelEx(&cfg, k_combine, cont);
        cfg.gridDim = dim3(Tt, Bb); cfg.blockDim = dim3(256);
        cfg.dynamicSmemBytes = (l == 0) ? 69632 : 52224;
        cudaLaunchKernelEx(&cfg, k_layer, l, gw, gb);
    }
    cfg.gridDim = dim3(1024); cfg.blockDim = dim3(256); cfg.dynamicSmemBytes = 0;
    cudaLaunchKernelEx(&cfg, k_head, prev, wih, whh, bih, bhh,
                       hw1, hb1, hw2, hb2, out);
}